// round 16
// baseline (speedup 1.0000x reference)
#include <cuda_runtime.h>
#include <cuda_bf16.h>
#include <cuda_fp16.h>
#include <math.h>
#include <stdint.h>

#define Bv   128
#define Lv   512
#define Hv   512
#define INv  64
#define OUTv 64
#define NHv  8
#define HORv 24
#define BH   (Bv * Hv)
#define ATT_OFF (Bv * HORv * OUTv)
#define KA   576                      // combined gates K = 64 (x) + 512 (h)

// ---------------- scratch (device globals; no allocation allowed) ----------------
__device__ __align__(16) __half g_K[(size_t)Bv * Lv * Hv];   // head-major [b][hn][l][64]
__device__ __align__(16) __half g_V[(size_t)Bv * Lv * Hv];
__device__ __align__(16) __half g_encF[(size_t)Bv * Lv * Hv];
__device__ __align__(16) __half g_WkF[Hv * Hv];
__device__ __align__(16) __half g_WvF[Hv * Hv];
__device__ __align__(16) __nv_bfloat16 g_WqH[Hv * Hv];
__device__ __align__(16) __nv_bfloat16 g_WqL[Hv * Hv];
__device__ __align__(16) __nv_bfloat16 g_Wgh[2048 * KA];     // gate-interleaved [4j+g][x|h]
__device__ __align__(16) __nv_bfloat16 g_Wgl[2048 * KA];
__device__ float g_bg[2048];                                 // reordered b_ih+b_hh
__device__ __align__(16) __nv_bfloat16 g_Ah[2 * Bv * KA];    // ping-pong A=[x|h] hi
__device__ __align__(16) __nv_bfloat16 g_Al[2 * Bv * KA];    // lo
__device__ float g_h[BH];
__device__ float g_c[BH];
__device__ float g_q[BH];                                    // q fp32 [b][512]
__device__ float g_Wcomb[OUTv * Hv];
__device__ float g_bcomb[OUTv];

__device__ __forceinline__ float sigmoidf_(float x) { return 1.f / (1.f + expf(-x)); }

__device__ __forceinline__ uint32_t smem_u32(const void* p) {
    uint32_t r;
    asm("{ .reg .u64 t; cvta.to.shared.u64 t, %1; cvt.u32.u64 %0, t; }" : "=r"(r) : "l"(p));
    return r;
}
__device__ __forceinline__ void cpa16(uint32_t s, const void* g) {
    asm volatile("cp.async.cg.shared.global [%0], [%1], 16;" :: "r"(s), "l"(g));
}
__device__ __forceinline__ void ldm_x4(uint32_t* r, uint32_t saddr) {
    asm volatile("ldmatrix.sync.aligned.m8n8.x4.shared.b16 {%0,%1,%2,%3}, [%4];"
                 : "=r"(r[0]), "=r"(r[1]), "=r"(r[2]), "=r"(r[3]) : "r"(saddr));
}
__device__ __forceinline__ void mma_bf16(float* d, const uint32_t* a, uint32_t b0, uint32_t b1) {
    asm volatile(
        "mma.sync.aligned.m16n8k16.row.col.f32.bf16.bf16.f32 "
        "{%0,%1,%2,%3}, {%4,%5,%6,%7}, {%8,%9}, {%0,%1,%2,%3};"
        : "+f"(d[0]), "+f"(d[1]), "+f"(d[2]), "+f"(d[3])
        : "r"(a[0]), "r"(a[1]), "r"(a[2]), "r"(a[3]), "r"(b0), "r"(b1));
}
__device__ __forceinline__ void mma_fp16(float* d, const uint32_t* a, uint32_t b0, uint32_t b1) {
    asm volatile(
        "mma.sync.aligned.m16n8k16.row.col.f32.f16.f16.f32 "
        "{%0,%1,%2,%3}, {%4,%5,%6,%7}, {%8,%9}, {%0,%1,%2,%3};"
        : "+f"(d[0]), "+f"(d[1]), "+f"(d[2]), "+f"(d[3])
        : "r"(a[0]), "r"(a[1]), "r"(a[2]), "r"(a[3]), "r"(b0), "r"(b1));
}

// ---------------- init: h0/c0 state + A0 = [x0 | h0] in bf16 hi/lo ----------------
__global__ void init_kernel(const float* __restrict__ h0, const float* __restrict__ c0,
                            const float* __restrict__ dec) {
    int i = blockIdx.x * 256 + threadIdx.x;
    if (i < BH) {
        float v = h0[i];
        g_h[i] = v;
        g_c[i] = c0[i];
        int m = i >> 9, j = i & 511;
        __nv_bfloat16 hb = __float2bfloat16(v);
        g_Ah[m * KA + 64 + j] = hb;
        g_Al[m * KA + 64 + j] = __float2bfloat16(v - __bfloat162float(hb));
    }
    if (i < Bv * INv) {
        float v = dec[i];
        int m = i >> 6, o = i & 63;
        __nv_bfloat16 xb = __float2bfloat16(v);
        g_Ah[m * KA + o] = xb;
        g_Al[m * KA + o] = __float2bfloat16(v - __bfloat162float(xb));
    }
}

// ---------------- Wk/Wv -> fp16, Wq -> bf16 hi/lo (one launch) ----------------
__global__ __launch_bounds__(256) void splitW_kernel(const float* __restrict__ Wk,
                                                     const float* __restrict__ Wv,
                                                     const float* __restrict__ Wq) {
    int i = blockIdx.x * 256 + threadIdx.x;        // 0 .. 3*65536-1 (float4 units)
    if (i < 131072) {
        const float* src = (i < 65536) ? Wk : Wv;
        __half* dst = (i < 65536) ? g_WkF : g_WvF;
        int j = i & 65535;
        float4 v = ((const float4*)src)[j];
        ((__half2*)dst)[2 * j]     = __floats2half2_rn(v.x, v.y);
        ((__half2*)dst)[2 * j + 1] = __floats2half2_rn(v.z, v.w);
    } else {
        int j = i - 131072;
        float4 v = ((const float4*)Wq)[j];
        __nv_bfloat162 hA = __floats2bfloat162_rn(v.x, v.y);
        __nv_bfloat162 hB = __floats2bfloat162_rn(v.z, v.w);
        __nv_bfloat162 lA = __floats2bfloat162_rn(v.x - __low2float(hA), v.y - __high2float(hA));
        __nv_bfloat162 lB = __floats2bfloat162_rn(v.z - __low2float(hB), v.w - __high2float(hB));
        ((__nv_bfloat162*)g_WqH)[2 * j]     = hA;
        ((__nv_bfloat162*)g_WqH)[2 * j + 1] = hB;
        ((__nv_bfloat162*)g_WqL)[2 * j]     = lA;
        ((__nv_bfloat162*)g_WqL)[2 * j + 1] = lB;
    }
}

// ---------------- enc fp32 -> fp16 over [base4, base4+n4) float4 range ----------------
__global__ __launch_bounds__(256) void encF_kernel(const float* __restrict__ src,
                                                   int base4, int n4) {
    int i = blockIdx.x * blockDim.x + threadIdx.x;
    int stride = gridDim.x * blockDim.x;
    for (; i < n4; i += stride) {
        int j = base4 + i;
        float4 v = ((const float4*)src)[j];
        ((__half2*)g_encF)[2 * j]     = __floats2half2_rn(v.x, v.y);
        ((__half2*)g_encF)[2 * j + 1] = __floats2half2_rn(v.z, v.w);
    }
}

// ---------------- gates weight reorder + split (+ bias) ----------------
__global__ __launch_bounds__(256) void wg_split_kernel(
    const float* __restrict__ W_ih, const float* __restrict__ W_hh,
    const float* __restrict__ b_ih, const float* __restrict__ b_hh) {
    int idx = blockIdx.x * 256 + threadIdx.x;      // 2048*576
    int r = idx / KA, c = idx - r * KA;
    int j = r >> 2, g = r & 3;
    int srow = g * 512 + j;
    float v = (c < 64) ? W_ih[srow * 64 + c] : W_hh[srow * 512 + (c - 64)];
    __nv_bfloat16 hb = __float2bfloat16(v);
    g_Wgh[idx] = hb;
    g_Wgl[idx] = __float2bfloat16(v - __bfloat162float(hb));
    if (idx < 2048) {
        int jj = idx >> 2, gg = idx & 3;
        g_bg[idx] = b_ih[gg * 512 + jj] + b_hh[gg * 512 + jj];
    }
}

// ---------------- one-time: Wcomb = Wfc @ Wo, bcomb = bfc + Wfc @ bo ----------------
__global__ __launch_bounds__(256) void comb_kernel(const float* __restrict__ Wfc,
                                                   const float* __restrict__ Wo) {
    int idx = blockIdx.x * 256 + threadIdx.x;   // 64*512 outputs
    int o = idx >> 9, k = idx & 511;
    float acc = 0.f;
#pragma unroll 4
    for (int j = 0; j < 512; j++) acc += Wfc[o * 512 + j] * Wo[j * 512 + k];
    g_Wcomb[idx] = acc;
}
__global__ void bcomb_kernel(const float* __restrict__ Wfc, const float* __restrict__ bo,
                             const float* __restrict__ bfc) {
    int o = threadIdx.x;
    float acc = bfc[o];
    for (int j = 0; j < 512; j++) acc += Wfc[o * 512 + j] * bo[j];
    g_bcomb[o] = acc;
}

// ---------------- KV projection: single-pass fp16 mma.sync, 128x128, 5 stages ----------------
#define KMAT   10240u                  // 128*40*2
#define KSTAGE (2u * KMAT)             // A + B = 20480
#define KV_SMEM (5u * KSTAGE)          // 102400

__global__ __launch_bounds__(256, 2) void kv_mma_kernel(
    const float* __restrict__ bk, const float* __restrict__ bv, int mbase) {
    extern __shared__ __align__(16) char smem[];
    const uint32_t sb = smem_u32(smem);
    const int tid = threadIdx.x, wid = tid >> 5, lane = tid & 31;
    const int nh = blockIdx.x & 3, tv = blockIdx.x >> 2;
    const int m0 = (mbase + blockIdx.y) * 128, n0 = nh * 128;
    const __half* __restrict__ Bp = tv ? g_WvF : g_WkF;
    const float* __restrict__ bias = tv ? bv : bk;
    __half* __restrict__ out = tv ? g_V : g_K;

    const int ldrow0 = tid >> 2, ldcol = (tid & 3) * 8;   // rows 0..63
    const int ldrow1 = ldrow0 + 64;
#define ISSUE_CHUNK(c, stage) do {                                              \
        const int _k0 = (c) * 32;                                               \
        uint32_t _s = sb + (uint32_t)(stage) * KSTAGE;                          \
        uint32_t _o0 = (uint32_t)(ldrow0 * 40 + ldcol) * 2;                     \
        uint32_t _o1 = (uint32_t)(ldrow1 * 40 + ldcol) * 2;                     \
        cpa16(_s + _o0, g_encF + (size_t)(m0 + ldrow0) * 512 + _k0 + ldcol);    \
        cpa16(_s + _o1, g_encF + (size_t)(m0 + ldrow1) * 512 + _k0 + ldcol);    \
        cpa16(_s + KMAT + _o0, Bp + (size_t)(n0 + ldrow0) * 512 + _k0 + ldcol); \
        cpa16(_s + KMAT + _o1, Bp + (size_t)(n0 + ldrow1) * 512 + _k0 + ldcol); \
        asm volatile("cp.async.commit_group;" ::: "memory");                    \
    } while (0)

    const int wm = wid >> 1, wn = wid & 1;   // warp tile: 32m x 64n
    float acc[2][8][4] = {};

    ISSUE_CHUNK(0, 0);
    ISSUE_CHUNK(1, 1);
    ISSUE_CHUNK(2, 2);
    ISSUE_CHUNK(3, 3);
    for (int c = 0; c < 16; c++) {
        if (c < 12) {
            ISSUE_CHUNK(c + 4, (c + 4) % 5);
            asm volatile("cp.async.wait_group 4;" ::: "memory");
        } else if (c == 12) {
            asm volatile("cp.async.wait_group 3;" ::: "memory");
        } else if (c == 13) {
            asm volatile("cp.async.wait_group 2;" ::: "memory");
        } else if (c == 14) {
            asm volatile("cp.async.wait_group 1;" ::: "memory");
        } else {
            asm volatile("cp.async.wait_group 0;" ::: "memory");
        }
        __syncthreads();
        const uint32_t sbase = sb + (uint32_t)(c % 5) * KSTAGE;
#pragma unroll
        for (int ks = 0; ks < 2; ks++) {
            uint32_t af[2][4], bf[4][4];
            const int kcol = ks * 16 + (lane >> 4) * 8;
#pragma unroll
            for (int mt = 0; mt < 2; mt++) {
                uint32_t r = sbase + (uint32_t)((wm * 32 + mt * 16 + (lane & 15)) * 40 + kcol) * 2;
                ldm_x4(af[mt], r);
            }
#pragma unroll
            for (int ng = 0; ng < 4; ng++) {
                uint32_t r = sbase + KMAT +
                             (uint32_t)((wn * 64 + ng * 16 + (lane & 15)) * 40 + kcol) * 2;
                ldm_x4(bf[ng], r);
            }
#pragma unroll
            for (int mt = 0; mt < 2; mt++)
#pragma unroll
                for (int nt = 0; nt < 8; nt++) {
                    const int ng = nt >> 1, hh = nt & 1;
                    mma_fp16(acc[mt][nt], af[mt], bf[ng][hh], bf[ng][2 + hh]);
                }
        }
        __syncthreads();
    }

    // epilogue: write head-major fp16 [b][hn][l][64]
    const int bidx = m0 >> 9;
#pragma unroll
    for (int mt = 0; mt < 2; mt++) {
        const int l0 = (m0 & 511) + wm * 32 + mt * 16 + (lane >> 2);
#pragma unroll
        for (int nt = 0; nt < 8; nt++) {
            const int col = n0 + wn * 64 + nt * 8 + (lane & 3) * 2;
            const int hng = col >> 6, d = col & 63;
            float2 bb = *(const float2*)(bias + col);
            size_t base = ((size_t)(bidx * 8 + hng) * 512 + l0) * 64 + d;
            *(__half2*)(out + base) =
                __floats2half2_rn(acc[mt][nt][0] + bb.x, acc[mt][nt][1] + bb.y);
            *(__half2*)(out + base + 8 * 64) =
                __floats2half2_rn(acc[mt][nt][2] + bb.x, acc[mt][nt][3] + bb.y);
        }
    }
}

// ---------------- gates: split-bf16 mma, 64-wide chunks, 4 stages + fused LSTM ----------------
#define GA_MAT   9216u                 // 64*72*2
#define GA_STAGE (4u * GA_MAT)         // 36864
#define GATES_SMEM (4u * GA_STAGE)     // 147456

__global__ __launch_bounds__(256) void gates_mma_kernel(int t) {
    extern __shared__ __align__(16) char smem[];
    const uint32_t sb = smem_u32(smem);
    const int tid = threadIdx.x, wid = tid >> 5, lane = tid & 31;
    const int m0 = (blockIdx.x & 1) * 64;
    const int n0 = (blockIdx.x >> 1) * 64;
    const __nv_bfloat16* __restrict__ Ah = g_Ah + (size_t)(t & 1) * Bv * KA;
    const __nv_bfloat16* __restrict__ Al = g_Al + (size_t)(t & 1) * Bv * KA;

    const int lr = tid >> 2, lcc = (tid & 3) * 8;   // rows 0..63, 2 col segs
#define G_ISSUE(c, stage) do {                                              \
        uint32_t _s = sb + (uint32_t)(stage) * GA_STAGE;                    \
        uint32_t _o = (uint32_t)(lr * 72 + lcc) * 2;                        \
        const __nv_bfloat16* _pa = Ah + (size_t)(m0 + lr) * KA + (c) * 64 + lcc;  \
        const __nv_bfloat16* _pl = Al + (size_t)(m0 + lr) * KA + (c) * 64 + lcc;  \
        const __nv_bfloat16* _ph = g_Wgh + (size_t)(n0 + lr) * KA + (c) * 64 + lcc; \
        const __nv_bfloat16* _pw = g_Wgl + (size_t)(n0 + lr) * KA + (c) * 64 + lcc; \
        cpa16(_s + 0 * GA_MAT + _o, _pa); cpa16(_s + 0 * GA_MAT + _o + 64, _pa + 32); \
        cpa16(_s + 1 * GA_MAT + _o, _pl); cpa16(_s + 1 * GA_MAT + _o + 64, _pl + 32); \
        cpa16(_s + 2 * GA_MAT + _o, _ph); cpa16(_s + 2 * GA_MAT + _o + 64, _ph + 32); \
        cpa16(_s + 3 * GA_MAT + _o, _pw); cpa16(_s + 3 * GA_MAT + _o + 64, _pw + 32); \
        asm volatile("cp.async.commit_group;" ::: "memory");                \
    } while (0)

    const int wm = wid & 1, wn = wid >> 1;   // warp tile 32m x 16n
    float acc[2][2][4] = {};

    G_ISSUE(0, 0);
    G_ISSUE(1, 1);
    G_ISSUE(2, 2);
    for (int c = 0; c < 9; c++) {
        if (c < 6) {
            G_ISSUE(c + 3, (c + 3) & 3);
            asm volatile("cp.async.wait_group 3;" ::: "memory");
        } else if (c == 6) {
            asm volatile("cp.async.wait_group 2;" ::: "memory");
        } else if (c == 7) {
            asm volatile("cp.async.wait_group 1;" ::: "memory");
        } else {
            asm volatile("cp.async.wait_group 0;" ::: "memory");
        }
        __syncthreads();
        const uint32_t sbase = sb + (uint32_t)(c & 3) * GA_STAGE;
#pragma unroll
        for (int ks = 0; ks < 4; ks++) {
            const int kcol = ks * 16 + (lane >> 4) * 8;
            uint32_t af[2][4], alf[2][4], bfr[4], blr[4];
#pragma unroll
            for (int mt = 0; mt < 2; mt++) {
                uint32_t r = sbase + (uint32_t)((wm * 32 + mt * 16 + (lane & 15)) * 72 + kcol) * 2;
                ldm_x4(af[mt], r);
                ldm_x4(alf[mt], r + GA_MAT);
            }
            {
                uint32_t r = sbase + 2 * GA_MAT +
                             (uint32_t)((wn * 16 + (lane & 15)) * 72 + kcol) * 2;
                ldm_x4(bfr, r);
                ldm_x4(blr, r + GA_MAT);
            }
#pragma unroll
            for (int mt = 0; mt < 2; mt++)
#pragma unroll
                for (int nt = 0; nt < 2; nt++) {
                    mma_bf16(acc[mt][nt], af[mt],  bfr[nt], bfr[2 + nt]);
                    mma_bf16(acc[mt][nt], af[mt],  blr[nt], blr[2 + nt]);
                    mma_bf16(acc[mt][nt], alf[mt], bfr[nt], bfr[2 + nt]);
                }
        }
        __syncthreads();
    }

    // ---- epilogue: stage gates (+bias) to smem, then fused LSTM pointwise ----
    float* sG = (float*)smem;            // [64][68]
    const int GS = 68;
#pragma unroll
    for (int mt = 0; mt < 2; mt++) {
        const int rl = wm * 32 + mt * 16 + (lane >> 2);
#pragma unroll
        for (int nt = 0; nt < 2; nt++) {
            const int cl = wn * 16 + nt * 8 + (lane & 3) * 2;
            float2 b2 = *(const float2*)(g_bg + n0 + cl);
            *(float2*)&sG[rl * GS + cl] =
                make_float2(acc[mt][nt][0] + b2.x, acc[mt][nt][1] + b2.y);
            *(float2*)&sG[(rl + 8) * GS + cl] =
                make_float2(acc[mt][nt][2] + b2.x, acc[mt][nt][3] + b2.y);
        }
    }
    __syncthreads();

    const int nbuf = (t + 1) & 1;
    __nv_bfloat16* __restrict__ Ahd = g_Ah + (size_t)nbuf * Bv * KA;
    __nv_bfloat16* __restrict__ Ald = g_Al + (size_t)nbuf * Bv * KA;
#pragma unroll
    for (int it = 0; it < 4; it++) {
        int item = tid + it * 256;         // 1024 = 64m x 16j
        int ml = item >> 4, j = item & 15;
        float4 gv = *(const float4*)&sG[ml * GS + j * 4];   // i,f,g,o
        int mg = m0 + ml, jg = (n0 >> 2) + j;
        float co = g_c[mg * 512 + jg];
        float iv = sigmoidf_(gv.x);
        float fv = sigmoidf_(gv.y);
        float gg = tanhf(gv.z);
        float ov = sigmoidf_(gv.w);
        float cc = fv * co + iv * gg;
        float hh = ov * tanhf(cc);
        g_c[mg * 512 + jg] = cc;
        g_h[mg * 512 + jg] = hh;
        __nv_bfloat16 hb = __float2bfloat16(hh);
        Ahd[mg * KA + 64 + jg] = hb;
        Ald[mg * KA + 64 + jg] = __float2bfloat16(hh - __bfloat162float(hb));
    }
}

// ---------------- q projection: split-bf16 mma, 64-wide chunks, 4 stages ----------------
#define QA_MAT_A 4608u                 // 32*72*2
#define QA_MAT_B 9216u                 // 64*72*2
#define QA_STAGE (2u * QA_MAT_A + 2u * QA_MAT_B)   // 27648
#define Q_SMEM   (4u * QA_STAGE)       // 110592

__global__ __launch_bounds__(256) void q_mma_kernel(const float* __restrict__ bq, int t) {
    extern __shared__ __align__(16) char smem[];
    const uint32_t sb = smem_u32(smem);
    const int tid = threadIdx.x, wid = tid >> 5, lane = tid & 31;
    const int m0 = (blockIdx.x & 3) * 32;
    const int n0 = (blockIdx.x >> 2) * 64;
    const int nbuf = (t + 1) & 1;
    const __nv_bfloat16* __restrict__ Ah = g_Ah + (size_t)nbuf * Bv * KA + 64;  // h section
    const __nv_bfloat16* __restrict__ Al = g_Al + (size_t)nbuf * Bv * KA + 64;

    const int lrA = tid >> 3, lcA = (tid & 7) * 8;   // A: 32 rows x 8 segs
    const int lrB = tid >> 2, lcB = (tid & 3) * 8;   // B: 64 rows x 2 segs each
#define Q_ISSUE(c, stage) do {                                              \
        uint32_t _s = sb + (uint32_t)(stage) * QA_STAGE;                    \
        uint32_t _oa = (uint32_t)(lrA * 72 + lcA) * 2;                      \
        uint32_t _ob = (uint32_t)(lrB * 72 + lcB) * 2;                      \
        const __nv_bfloat16* _pa = Ah + (size_t)(m0 + lrA) * KA + (c) * 64 + lcA;  \
        const __nv_bfloat16* _pl = Al + (size_t)(m0 + lrA) * KA + (c) * 64 + lcA;  \
        const __nv_bfloat16* _ph = g_WqH + (size_t)(n0 + lrB) * 512 + (c) * 64 + lcB; \
        const __nv_bfloat16* _pw = g_WqL + (size_t)(n0 + lrB) * 512 + (c) * 64 + lcB; \
        cpa16(_s + _oa, _pa);                                               \
        cpa16(_s + QA_MAT_A + _oa, _pl);                                    \
        cpa16(_s + 2 * QA_MAT_A + _ob, _ph);                                \
        cpa16(_s + 2 * QA_MAT_A + _ob + 64, _ph + 32);                      \
        cpa16(_s + 2 * QA_MAT_A + QA_MAT_B + _ob, _pw);                     \
        cpa16(_s + 2 * QA_MAT_A + QA_MAT_B + _ob + 64, _pw + 32);           \
        asm volatile("cp.async.commit_group;" ::: "memory");                \
    } while (0)

    const int wm = wid & 1, wn = wid >> 1;   // warp tile 16m x 16n
    float acc[2][4] = {};

    Q_ISSUE(0, 0);
    Q_ISSUE(1, 1);
    Q_ISSUE(2, 2);
    for (int c = 0; c < 8; c++) {
        if (c < 5) {
            Q_ISSUE(c + 3, (c + 3) & 3);
            asm volatile("cp.async.wait_group 3;" ::: "memory");
        } else if (c == 5) {
            asm volatile("cp.async.wait_group 2;" ::: "memory");
        } else if (c == 6) {
            asm volatile("cp.async.wait_group 1;" ::: "memory");
        } else {
            asm volatile("cp.async.wait_group 0;" ::: "memory");
        }
        __syncthreads();
        const uint32_t sbase = sb + (uint32_t)(c & 3) * QA_STAGE;
#pragma unroll
        for (int ks = 0; ks < 4; ks++) {
            const int kcol = ks * 16 + (lane >> 4) * 8;
            uint32_t af[4], alf[4], bfr[4], blr[4];
            {
                uint32_t r = sbase + (uint32_t)((wm * 16 + (lane & 15)) * 72 + kcol) * 2;
                ldm_x4(af, r);
                ldm_x4(alf, r + QA_MAT_A);
            }
            {
                uint32_t r = sbase + 2 * QA_MAT_A +
                             (uint32_t)((wn * 16 + (lane & 15)) * 72 + kcol) * 2;
                ldm_x4(bfr, r);
                ldm_x4(blr, r + QA_MAT_B);
            }
#pragma unroll
            for (int nt = 0; nt < 2; nt++) {
                mma_bf16(acc[nt], af,  bfr[nt], bfr[2 + nt]);
                mma_bf16(acc[nt], af,  blr[nt], blr[2 + nt]);
                mma_bf16(acc[nt], alf, bfr[nt], bfr[2 + nt]);
            }
        }
        __syncthreads();
    }

    // epilogue: q = acc + bq -> g_q fp32
    const int row = m0 + wm * 16 + (lane >> 2);
#pragma unroll
    for (int nt = 0; nt < 2; nt++) {
        const int col = n0 + wn * 16 + nt * 8 + (lane & 3) * 2;
        float2 b2 = *(const float2*)(bq + col);
        *(float2*)(g_q + (size_t)row * 512 + col) =
            make_float2(acc[nt][0] + b2.x, acc[nt][1] + b2.y);
        *(float2*)(g_q + (size_t)(row + 8) * 512 + col) =
            make_float2(acc[nt][2] + b2.x, acc[nt][3] + b2.y);
    }
}

// ---------------- fused attention + pred: 1 block per batch, 512 threads ----------------
__global__ __launch_bounds__(512) void attn_pred_kernel(float* __restrict__ dout, int t) {
    const int b = (t & 1) ? (int)(gridDim.x - 1 - blockIdx.x) : (int)blockIdx.x;
    const int tid = threadIdx.x;
    const int wid = tid >> 5, lane = tid & 31;
    const int head = wid >> 1, wh = wid & 1;    // 2 warps per head
    __shared__ float sq[512];
    __shared__ float ss[NHv][512];
    __shared__ float red[16];
    __shared__ float bcst[NHv];
    __shared__ float spx[NHv][2][64];
    __shared__ float sctx[512];
    const float scale = 0.125f;   // 1/sqrt(64)

    sq[tid] = g_q[(size_t)b * 512 + tid];
    __syncthreads();

    const __half* __restrict__ Kb = g_K + (size_t)(b * NHv + head) * Lv * 64;
    const __half* __restrict__ Vb = g_V + (size_t)(b * NHv + head) * Lv * 64;
    const float* __restrict__ qh = sq + head * 64;

    // ---- scores: 8 lanes per row; warp = 4 rows/iter, 64 iters over 512 rows ----
    const int rr = lane >> 3, cc = lane & 7;
    float q8[8];
#pragma unroll
    for (int j = 0; j < 8; j++) q8[j] = qh[cc * 8 + j];
    float mxl = -1e30f;
#pragma unroll 8
    for (int iter = 0; iter < 64; iter++) {
        const int row = iter * 8 + wh * 4 + rr;
        uint4 u = *(const uint4*)(Kb + (size_t)row * 64 + cc * 8);
        const __half2* hp = (const __half2*)&u;
        float s = 0.f;
#pragma unroll
        for (int j = 0; j < 4; j++) {
            float2 kf = __half22float2(hp[j]);
            s += kf.x * q8[j * 2] + kf.y * q8[j * 2 + 1];
        }
        s += __shfl_xor_sync(0xffffffffu, s, 1);
        s += __shfl_xor_sync(0xffffffffu, s, 2);
        s += __shfl_xor_sync(0xffffffffu, s, 4);
        s *= scale;
        if (cc == 0) ss[head][row] = s;
        mxl = fmaxf(mxl, s);
    }
    // per-head max across 2 warps
#pragma unroll
    for (int off = 16; off > 0; off >>= 1)
        mxl = fmaxf(mxl, __shfl_xor_sync(0xffffffffu, mxl, off));
    if (lane == 0) red[wid] = mxl;
    __syncthreads();
    if (tid < NHv) bcst[tid] = fmaxf(red[2 * tid], red[2 * tid + 1]);
    __syncthreads();
    const float mx = bcst[head];
    // exp + per-head sum: thread handles 8 contiguous rows
    {
        const int r0 = wh * 256 + lane * 8;
        float sm = 0.f;
        float e[8];
#pragma unroll
        for (int j = 0; j < 8; j++) {
            e[j] = expf(ss[head][r0 + j] - mx);
            sm += e[j];
        }
#pragma unroll
        for (int j = 0; j < 8; j++) ss[head][r0 + j] = e[j];
#pragma unroll
        for (int off = 16; off > 0; off >>= 1) sm += __shfl_xor_sync(0xffffffffu, sm, off);
        __syncthreads();
        if (lane == 0) red[wid] = sm;
        __syncthreads();
        if (tid < NHv) bcst[tid] = 1.f / (red[2 * tid] + red[2 * tid + 1]);
        __syncthreads();
        const float inv = bcst[head];
        float* amap = dout + ATT_OFF + ((size_t)(b * NHv + head) * HORv + t) * Lv;
#pragma unroll
        for (int j = 0; j < 8; j++) {
            float a = e[j] * inv;
            ss[head][r0 + j] = a;
            amap[r0 + j] = a;
        }
    }
    __syncthreads();

    // ---- context: warp handles 256 rows, lane owns d-pair (128B/instr) ----
    {
        float2 acc2 = make_float2(0.f, 0.f);
        const __half* vp = Vb + (size_t)(wh * 256) * 64 + lane * 2;
        const float* sa = &ss[head][wh * 256];
#pragma unroll 8
        for (int l = 0; l < 256; l++) {
            float a = sa[l];
            float2 v = __half22float2(*(const __half2*)(vp + (size_t)l * 64));
            acc2.x += a * v.x;
            acc2.y += a * v.y;
        }
        *(float2*)&spx[head][wh][lane * 2] = acc2;
    }
    __syncthreads();
    {
        const int hh = tid >> 6, d = tid & 63;
        sctx[tid] = spx[hh][0][d] + spx[hh][1][d];
    }
    __syncthreads();

    // ---- fused pred: 16 warps x 4 outputs; pred = ctx @ Wcomb^T + bcomb ----
    const int nbuf = (t + 1) & 1;
#pragma unroll
    for (int p = 0; p < 4; p++) {
        const int o = p * 16 + wid;
        const float4* w4 = (const float4*)(g_Wcomb + (size_t)o * Hv);
        const float4* c4 = (const float4*)sctx;
        float acc = 0.f;
#pragma unroll
        for (int i = 0; i < 4; i++) {
            float4 a = c4[i * 32 + lane], ww = w4[i * 32 + lane];
            acc += a.x * ww.x + a.y * ww.y + a.z * ww.z + a.w * ww.w;
        }
#pragma unroll
        for (int off = 16; off > 0; off >>= 1) acc += __shfl_xor_sync(0xffffffffu, acc, off);
        if (lane == 0) {
            float v = acc + g_bcomb[o];
            __nv_bfloat16 xb = __float2bfloat16(v);
            g_Ah[(size_t)nbuf * Bv * KA + b * KA + o] = xb;
            g_Al[(size_t)nbuf * Bv * KA + b * KA + o] =
                __float2bfloat16(v - __bfloat162float(xb));
            dout[(size_t)b * HORv * OUTv + t * OUTv + o] = v;
        }
    }
}

// ---------------- host launcher ----------------
extern "C" void kernel_launch(void* const* d_in, const int* in_sizes, int n_in,
                              void* d_out, int out_size) {
    const float* enc  = (const float*)d_in[0];
    const float* h0   = (const float*)d_in[1];
    const float* c0   = (const float*)d_in[2];
    const float* dec  = (const float*)d_in[3];
    const float* W_ih = (const float*)d_in[4];
    const float* W_hh = (const float*)d_in[5];
    const float* b_ih = (const float*)d_in[6];
    const float* b_hh = (const float*)d_in[7];
    const float* Wq   = (const float*)d_in[8];
    const float* bq   = (const float*)d_in[9];
    const float* Wk   = (const float*)d_in[10];
    const float* bk   = (const float*)d_in[11];
    const float* Wv   = (const float*)d_in[12];
    const float* bv   = (const float*)d_in[13];
    const float* Wo   = (const float*)d_in[14];
    const float* bo   = (const float*)d_in[15];
    const float* Wfc  = (const float*)d_in[16];
    const float* bfc  = (const float*)d_in[17];
    float* out = (float*)d_out;

    static cudaStream_t s2 = nullptr;
    static cudaEvent_t evFork = nullptr, evInit = nullptr, evW = nullptr;
    static cudaEvent_t evE1 = nullptr, evJoin = nullptr;
    if (!s2) {
        cudaFuncSetAttribute(kv_mma_kernel, cudaFuncAttributeMaxDynamicSharedMemorySize,
                             KV_SMEM);
        cudaFuncSetAttribute(gates_mma_kernel, cudaFuncAttributeMaxDynamicSharedMemorySize,
                             GATES_SMEM);
        cudaFuncSetAttribute(q_mma_kernel, cudaFuncAttributeMaxDynamicSharedMemorySize,
                             Q_SMEM);
        cudaStreamCreateWithFlags(&s2, cudaStreamNonBlocking);
        cudaEventCreateWithFlags(&evFork, cudaEventDisableTiming);
        cudaEventCreateWithFlags(&evInit, cudaEventDisableTiming);
        cudaEventCreateWithFlags(&evW, cudaEventDisableTiming);
        cudaEventCreateWithFlags(&evE1, cudaEventDisableTiming);
        cudaEventCreateWithFlags(&evJoin, cudaEventDisableTiming);
    }

    const int half4 = (Bv * Lv * Hv) / 8;   // float4 units per half

    // fork side stream: splitW + encF(second half) run under init/encF0/kv0
    cudaEventRecord(evFork, 0);
    cudaStreamWaitEvent(s2, evFork, 0);
    splitW_kernel<<<768, 256, 0, s2>>>(Wk, Wv, Wq);
    cudaEventRecord(evW, s2);
    encF_kernel<<<1024, 256, 0, s2>>>(enc, half4, half4);
    cudaEventRecord(evE1, s2);

    // main stream: init + first-half enc conversion, then first kv half
    init_kernel<<<(BH + 255) / 256, 256>>>(h0, c0, dec);
    cudaEventRecord(evInit, 0);
    encF_kernel<<<1024, 256>>>(enc, 0, half4);
    cudaStreamWaitEvent(0, evW, 0);
    kv_mma_kernel<<<dim3(8, 256), 256, KV_SMEM>>>(bk, bv, 0);
    cudaStreamWaitEvent(0, evE1, 0);
    kv_mma_kernel<<<dim3(8, 256), 256, KV_SMEM>>>(bk, bv, 256);

    // side stream (overlaps with kv halves): weight prep + step-0 gates/q
    cudaStreamWaitEvent(s2, evInit, 0);
    wg_split_kernel<<<(2048 * KA) / 256, 256, 0, s2>>>(W_ih, W_hh, b_ih, b_hh);
    comb_kernel<<<(OUTv * Hv) / 256, 256, 0, s2>>>(Wfc, Wo);
    bcomb_kernel<<<1, 64, 0, s2>>>(Wfc, bo, bfc);
    gates_mma_kernel<<<64, 256, GATES_SMEM, s2>>>(0);
    q_mma_kernel<<<32, 256, Q_SMEM, s2>>>(bq, 0);
    cudaEventRecord(evJoin, s2);
    cudaStreamWaitEvent(0, evJoin, 0);

    // main stream: step 0 tail + remaining steps (3 kernels/step)
    attn_pred_kernel<<<Bv, 512>>>(out, 0);
    for (int t = 1; t < HORv; t++) {
        gates_mma_kernel<<<64, 256, GATES_SMEM>>>(t);
        q_mma_kernel<<<32, 256, Q_SMEM>>>(bq, t);
        attn_pred_kernel<<<Bv, 512>>>(out, t);
    }
}

// round 17
// speedup vs baseline: 1.2596x; 1.2596x over previous
#include <cuda_runtime.h>
#include <cuda_bf16.h>
#include <cuda_fp16.h>
#include <math.h>
#include <stdint.h>

#define Bv   128
#define Lv   512
#define Hv   512
#define INv  64
#define OUTv 64
#define NHv  8
#define HORv 24
#define BH   (Bv * Hv)
#define ATT_OFF (Bv * HORv * OUTv)
#define KA   576                      // combined gates K = 64 (x) + 512 (h)

// ---------------- scratch (device globals; no allocation allowed) ----------------
__device__ __align__(16) __half g_K[(size_t)Bv * Lv * Hv];   // head-major [b][hn][l][64]
__device__ __align__(16) __half g_V[(size_t)Bv * Lv * Hv];
__device__ __align__(16) __half g_encF[(size_t)Bv * Lv * Hv];
__device__ __align__(16) __half g_WkF[Hv * Hv];
__device__ __align__(16) __half g_WvF[Hv * Hv];
__device__ __align__(16) __nv_bfloat16 g_WqH[Hv * Hv];
__device__ __align__(16) __nv_bfloat16 g_WqL[Hv * Hv];
__device__ __align__(16) __nv_bfloat16 g_Wgh[2048 * KA];     // gate-interleaved [4j+g][x|h]
__device__ __align__(16) __nv_bfloat16 g_Wgl[2048 * KA];
__device__ float g_bg[2048];                                 // reordered b_ih+b_hh
__device__ __align__(16) __nv_bfloat16 g_Ah[2 * Bv * KA];    // ping-pong A=[x|h] hi
__device__ __align__(16) __nv_bfloat16 g_Al[2 * Bv * KA];    // lo
__device__ float g_h[BH];
__device__ float g_c[BH];
__device__ float g_q[BH];                                    // q fp32 [b][512]
__device__ float g_ctx[BH];
__device__ float g_Wcomb[OUTv * Hv];
__device__ float g_bcomb[OUTv];

__device__ __forceinline__ float sigmoidf_(float x) { return 1.f / (1.f + expf(-x)); }

__device__ __forceinline__ uint32_t smem_u32(const void* p) {
    uint32_t r;
    asm("{ .reg .u64 t; cvta.to.shared.u64 t, %1; cvt.u32.u64 %0, t; }" : "=r"(r) : "l"(p));
    return r;
}
__device__ __forceinline__ void cpa16(uint32_t s, const void* g) {
    asm volatile("cp.async.cg.shared.global [%0], [%1], 16;" :: "r"(s), "l"(g));
}
__device__ __forceinline__ void ldm_x4(uint32_t* r, uint32_t saddr) {
    asm volatile("ldmatrix.sync.aligned.m8n8.x4.shared.b16 {%0,%1,%2,%3}, [%4];"
                 : "=r"(r[0]), "=r"(r[1]), "=r"(r[2]), "=r"(r[3]) : "r"(saddr));
}
__device__ __forceinline__ void mma_bf16(float* d, const uint32_t* a, uint32_t b0, uint32_t b1) {
    asm volatile(
        "mma.sync.aligned.m16n8k16.row.col.f32.bf16.bf16.f32 "
        "{%0,%1,%2,%3}, {%4,%5,%6,%7}, {%8,%9}, {%0,%1,%2,%3};"
        : "+f"(d[0]), "+f"(d[1]), "+f"(d[2]), "+f"(d[3])
        : "r"(a[0]), "r"(a[1]), "r"(a[2]), "r"(a[3]), "r"(b0), "r"(b1));
}
__device__ __forceinline__ void mma_fp16(float* d, const uint32_t* a, uint32_t b0, uint32_t b1) {
    asm volatile(
        "mma.sync.aligned.m16n8k16.row.col.f32.f16.f16.f32 "
        "{%0,%1,%2,%3}, {%4,%5,%6,%7}, {%8,%9}, {%0,%1,%2,%3};"
        : "+f"(d[0]), "+f"(d[1]), "+f"(d[2]), "+f"(d[3])
        : "r"(a[0]), "r"(a[1]), "r"(a[2]), "r"(a[3]), "r"(b0), "r"(b1));
}

// ---------------- init: h0/c0 state + A0 = [x0 | h0] in bf16 hi/lo ----------------
__global__ void init_kernel(const float* __restrict__ h0, const float* __restrict__ c0,
                            const float* __restrict__ dec) {
    int i = blockIdx.x * 256 + threadIdx.x;
    if (i < BH) {
        float v = h0[i];
        g_h[i] = v;
        g_c[i] = c0[i];
        int m = i >> 9, j = i & 511;
        __nv_bfloat16 hb = __float2bfloat16(v);
        g_Ah[m * KA + 64 + j] = hb;
        g_Al[m * KA + 64 + j] = __float2bfloat16(v - __bfloat162float(hb));
    }
    if (i < Bv * INv) {
        float v = dec[i];
        int m = i >> 6, o = i & 63;
        __nv_bfloat16 xb = __float2bfloat16(v);
        g_Ah[m * KA + o] = xb;
        g_Al[m * KA + o] = __float2bfloat16(v - __bfloat162float(xb));
    }
}

// ---------------- Wk/Wv -> fp16, Wq -> bf16 hi/lo (one launch) ----------------
__global__ __launch_bounds__(256) void splitW_kernel(const float* __restrict__ Wk,
                                                     const float* __restrict__ Wv,
                                                     const float* __restrict__ Wq) {
    int i = blockIdx.x * 256 + threadIdx.x;        // 0 .. 3*65536-1 (float4 units)
    if (i < 131072) {
        const float* src = (i < 65536) ? Wk : Wv;
        __half* dst = (i < 65536) ? g_WkF : g_WvF;
        int j = i & 65535;
        float4 v = ((const float4*)src)[j];
        ((__half2*)dst)[2 * j]     = __floats2half2_rn(v.x, v.y);
        ((__half2*)dst)[2 * j + 1] = __floats2half2_rn(v.z, v.w);
    } else {
        int j = i - 131072;
        float4 v = ((const float4*)Wq)[j];
        __nv_bfloat162 hA = __floats2bfloat162_rn(v.x, v.y);
        __nv_bfloat162 hB = __floats2bfloat162_rn(v.z, v.w);
        __nv_bfloat162 lA = __floats2bfloat162_rn(v.x - __low2float(hA), v.y - __high2float(hA));
        __nv_bfloat162 lB = __floats2bfloat162_rn(v.z - __low2float(hB), v.w - __high2float(hB));
        ((__nv_bfloat162*)g_WqH)[2 * j]     = hA;
        ((__nv_bfloat162*)g_WqH)[2 * j + 1] = hB;
        ((__nv_bfloat162*)g_WqL)[2 * j]     = lA;
        ((__nv_bfloat162*)g_WqL)[2 * j + 1] = lB;
    }
}

// ---------------- enc fp32 -> fp16 over [base4, base4+n4) float4 range ----------------
__global__ __launch_bounds__(256) void encF_kernel(const float* __restrict__ src,
                                                   int base4, int n4) {
    int i = blockIdx.x * blockDim.x + threadIdx.x;
    int stride = gridDim.x * blockDim.x;
    for (; i < n4; i += stride) {
        int j = base4 + i;
        float4 v = ((const float4*)src)[j];
        ((__half2*)g_encF)[2 * j]     = __floats2half2_rn(v.x, v.y);
        ((__half2*)g_encF)[2 * j + 1] = __floats2half2_rn(v.z, v.w);
    }
}

// ---------------- gates weight reorder + split (+ bias) ----------------
__global__ __launch_bounds__(256) void wg_split_kernel(
    const float* __restrict__ W_ih, const float* __restrict__ W_hh,
    const float* __restrict__ b_ih, const float* __restrict__ b_hh) {
    int idx = blockIdx.x * 256 + threadIdx.x;      // 2048*576
    int r = idx / KA, c = idx - r * KA;
    int j = r >> 2, g = r & 3;
    int srow = g * 512 + j;
    float v = (c < 64) ? W_ih[srow * 64 + c] : W_hh[srow * 512 + (c - 64)];
    __nv_bfloat16 hb = __float2bfloat16(v);
    g_Wgh[idx] = hb;
    g_Wgl[idx] = __float2bfloat16(v - __bfloat162float(hb));
    if (idx < 2048) {
        int jj = idx >> 2, gg = idx & 3;
        g_bg[idx] = b_ih[gg * 512 + jj] + b_hh[gg * 512 + jj];
    }
}

// ---------------- one-time: Wcomb = Wfc @ Wo, bcomb = bfc + Wfc @ bo ----------------
__global__ __launch_bounds__(256) void comb_kernel(const float* __restrict__ Wfc,
                                                   const float* __restrict__ Wo) {
    int idx = blockIdx.x * 256 + threadIdx.x;   // 64*512 outputs
    int o = idx >> 9, k = idx & 511;
    float acc = 0.f;
#pragma unroll 4
    for (int j = 0; j < 512; j++) acc += Wfc[o * 512 + j] * Wo[j * 512 + k];
    g_Wcomb[idx] = acc;
}
__global__ void bcomb_kernel(const float* __restrict__ Wfc, const float* __restrict__ bo,
                             const float* __restrict__ bfc) {
    int o = threadIdx.x;
    float acc = bfc[o];
    for (int j = 0; j < 512; j++) acc += Wfc[o * 512 + j] * bo[j];
    g_bcomb[o] = acc;
}

// ---------------- KV projection: single-pass fp16 mma.sync, 128x128, 5 stages ----------------
#define KMAT   10240u                  // 128*40*2
#define KSTAGE (2u * KMAT)             // A + B = 20480
#define KV_SMEM (5u * KSTAGE)          // 102400

__global__ __launch_bounds__(256, 2) void kv_mma_kernel(
    const float* __restrict__ bk, const float* __restrict__ bv, int mbase) {
    extern __shared__ __align__(16) char smem[];
    const uint32_t sb = smem_u32(smem);
    const int tid = threadIdx.x, wid = tid >> 5, lane = tid & 31;
    const int nh = blockIdx.x & 3, tv = blockIdx.x >> 2;
    const int m0 = (mbase + blockIdx.y) * 128, n0 = nh * 128;
    const __half* __restrict__ Bp = tv ? g_WvF : g_WkF;
    const float* __restrict__ bias = tv ? bv : bk;
    __half* __restrict__ out = tv ? g_V : g_K;

    const int ldrow0 = tid >> 2, ldcol = (tid & 3) * 8;   // rows 0..63
    const int ldrow1 = ldrow0 + 64;
#define ISSUE_CHUNK(c, stage) do {                                              \
        const int _k0 = (c) * 32;                                               \
        uint32_t _s = sb + (uint32_t)(stage) * KSTAGE;                          \
        uint32_t _o0 = (uint32_t)(ldrow0 * 40 + ldcol) * 2;                     \
        uint32_t _o1 = (uint32_t)(ldrow1 * 40 + ldcol) * 2;                     \
        cpa16(_s + _o0, g_encF + (size_t)(m0 + ldrow0) * 512 + _k0 + ldcol);    \
        cpa16(_s + _o1, g_encF + (size_t)(m0 + ldrow1) * 512 + _k0 + ldcol);    \
        cpa16(_s + KMAT + _o0, Bp + (size_t)(n0 + ldrow0) * 512 + _k0 + ldcol); \
        cpa16(_s + KMAT + _o1, Bp + (size_t)(n0 + ldrow1) * 512 + _k0 + ldcol); \
        asm volatile("cp.async.commit_group;" ::: "memory");                    \
    } while (0)

    const int wm = wid >> 1, wn = wid & 1;   // warp tile: 32m x 64n
    float acc[2][8][4] = {};

    ISSUE_CHUNK(0, 0);
    ISSUE_CHUNK(1, 1);
    ISSUE_CHUNK(2, 2);
    ISSUE_CHUNK(3, 3);
    for (int c = 0; c < 16; c++) {
        if (c < 12) {
            ISSUE_CHUNK(c + 4, (c + 4) % 5);
            asm volatile("cp.async.wait_group 4;" ::: "memory");
        } else if (c == 12) {
            asm volatile("cp.async.wait_group 3;" ::: "memory");
        } else if (c == 13) {
            asm volatile("cp.async.wait_group 2;" ::: "memory");
        } else if (c == 14) {
            asm volatile("cp.async.wait_group 1;" ::: "memory");
        } else {
            asm volatile("cp.async.wait_group 0;" ::: "memory");
        }
        __syncthreads();
        const uint32_t sbase = sb + (uint32_t)(c % 5) * KSTAGE;
#pragma unroll
        for (int ks = 0; ks < 2; ks++) {
            uint32_t af[2][4], bf[4][4];
            const int kcol = ks * 16 + (lane >> 4) * 8;
#pragma unroll
            for (int mt = 0; mt < 2; mt++) {
                uint32_t r = sbase + (uint32_t)((wm * 32 + mt * 16 + (lane & 15)) * 40 + kcol) * 2;
                ldm_x4(af[mt], r);
            }
#pragma unroll
            for (int ng = 0; ng < 4; ng++) {
                uint32_t r = sbase + KMAT +
                             (uint32_t)((wn * 64 + ng * 16 + (lane & 15)) * 40 + kcol) * 2;
                ldm_x4(bf[ng], r);
            }
#pragma unroll
            for (int mt = 0; mt < 2; mt++)
#pragma unroll
                for (int nt = 0; nt < 8; nt++) {
                    const int ng = nt >> 1, hh = nt & 1;
                    mma_fp16(acc[mt][nt], af[mt], bf[ng][hh], bf[ng][2 + hh]);
                }
        }
        __syncthreads();
    }

    // epilogue: write head-major fp16 [b][hn][l][64]
    const int bidx = m0 >> 9;
#pragma unroll
    for (int mt = 0; mt < 2; mt++) {
        const int l0 = (m0 & 511) + wm * 32 + mt * 16 + (lane >> 2);
#pragma unroll
        for (int nt = 0; nt < 8; nt++) {
            const int col = n0 + wn * 64 + nt * 8 + (lane & 3) * 2;
            const int hng = col >> 6, d = col & 63;
            float2 bb = *(const float2*)(bias + col);
            size_t base = ((size_t)(bidx * 8 + hng) * 512 + l0) * 64 + d;
            *(__half2*)(out + base) =
                __floats2half2_rn(acc[mt][nt][0] + bb.x, acc[mt][nt][1] + bb.y);
            *(__half2*)(out + base + 8 * 64) =
                __floats2half2_rn(acc[mt][nt][2] + bb.x, acc[mt][nt][3] + bb.y);
        }
    }
}

// ---------------- gates: split-bf16 mma, 64-wide chunks, 4 stages + fused LSTM ----------------
#define GA_MAT   9216u                 // 64*72*2
#define GA_STAGE (4u * GA_MAT)         // 36864
#define GATES_SMEM (4u * GA_STAGE)     // 147456

__global__ __launch_bounds__(256) void gates_mma_kernel(int t) {
    extern __shared__ __align__(16) char smem[];
    const uint32_t sb = smem_u32(smem);
    const int tid = threadIdx.x, wid = tid >> 5, lane = tid & 31;
    const int m0 = (blockIdx.x & 1) * 64;
    const int n0 = (blockIdx.x >> 1) * 64;
    const __nv_bfloat16* __restrict__ Ah = g_Ah + (size_t)(t & 1) * Bv * KA;
    const __nv_bfloat16* __restrict__ Al = g_Al + (size_t)(t & 1) * Bv * KA;

    const int lr = tid >> 2, lcc = (tid & 3) * 8;   // rows 0..63, 2 col segs
#define G_ISSUE(c, stage) do {                                              \
        uint32_t _s = sb + (uint32_t)(stage) * GA_STAGE;                    \
        uint32_t _o = (uint32_t)(lr * 72 + lcc) * 2;                        \
        const __nv_bfloat16* _pa = Ah + (size_t)(m0 + lr) * KA + (c) * 64 + lcc;  \
        const __nv_bfloat16* _pl = Al + (size_t)(m0 + lr) * KA + (c) * 64 + lcc;  \
        const __nv_bfloat16* _ph = g_Wgh + (size_t)(n0 + lr) * KA + (c) * 64 + lcc; \
        const __nv_bfloat16* _pw = g_Wgl + (size_t)(n0 + lr) * KA + (c) * 64 + lcc; \
        cpa16(_s + 0 * GA_MAT + _o, _pa); cpa16(_s + 0 * GA_MAT + _o + 64, _pa + 32); \
        cpa16(_s + 1 * GA_MAT + _o, _pl); cpa16(_s + 1 * GA_MAT + _o + 64, _pl + 32); \
        cpa16(_s + 2 * GA_MAT + _o, _ph); cpa16(_s + 2 * GA_MAT + _o + 64, _ph + 32); \
        cpa16(_s + 3 * GA_MAT + _o, _pw); cpa16(_s + 3 * GA_MAT + _o + 64, _pw + 32); \
        asm volatile("cp.async.commit_group;" ::: "memory");                \
    } while (0)

    const int wm = wid & 1, wn = wid >> 1;   // warp tile 32m x 16n
    float acc[2][2][4] = {};

    G_ISSUE(0, 0);
    G_ISSUE(1, 1);
    G_ISSUE(2, 2);
    for (int c = 0; c < 9; c++) {
        if (c < 6) {
            G_ISSUE(c + 3, (c + 3) & 3);
            asm volatile("cp.async.wait_group 3;" ::: "memory");
        } else if (c == 6) {
            asm volatile("cp.async.wait_group 2;" ::: "memory");
        } else if (c == 7) {
            asm volatile("cp.async.wait_group 1;" ::: "memory");
        } else {
            asm volatile("cp.async.wait_group 0;" ::: "memory");
        }
        __syncthreads();
        const uint32_t sbase = sb + (uint32_t)(c & 3) * GA_STAGE;
#pragma unroll
        for (int ks = 0; ks < 4; ks++) {
            const int kcol = ks * 16 + (lane >> 4) * 8;
            uint32_t af[2][4], alf[2][4], bfr[4], blr[4];
#pragma unroll
            for (int mt = 0; mt < 2; mt++) {
                uint32_t r = sbase + (uint32_t)((wm * 32 + mt * 16 + (lane & 15)) * 72 + kcol) * 2;
                ldm_x4(af[mt], r);
                ldm_x4(alf[mt], r + GA_MAT);
            }
            {
                uint32_t r = sbase + 2 * GA_MAT +
                             (uint32_t)((wn * 16 + (lane & 15)) * 72 + kcol) * 2;
                ldm_x4(bfr, r);
                ldm_x4(blr, r + GA_MAT);
            }
#pragma unroll
            for (int mt = 0; mt < 2; mt++)
#pragma unroll
                for (int nt = 0; nt < 2; nt++) {
                    mma_bf16(acc[mt][nt], af[mt],  bfr[nt], bfr[2 + nt]);
                    mma_bf16(acc[mt][nt], af[mt],  blr[nt], blr[2 + nt]);
                    mma_bf16(acc[mt][nt], alf[mt], bfr[nt], bfr[2 + nt]);
                }
        }
        __syncthreads();
    }

    // ---- epilogue: stage gates (+bias) to smem, then fused LSTM pointwise ----
    float* sG = (float*)smem;            // [64][68]
    const int GS = 68;
#pragma unroll
    for (int mt = 0; mt < 2; mt++) {
        const int rl = wm * 32 + mt * 16 + (lane >> 2);
#pragma unroll
        for (int nt = 0; nt < 2; nt++) {
            const int cl = wn * 16 + nt * 8 + (lane & 3) * 2;
            float2 b2 = *(const float2*)(g_bg + n0 + cl);
            *(float2*)&sG[rl * GS + cl] =
                make_float2(acc[mt][nt][0] + b2.x, acc[mt][nt][1] + b2.y);
            *(float2*)&sG[(rl + 8) * GS + cl] =
                make_float2(acc[mt][nt][2] + b2.x, acc[mt][nt][3] + b2.y);
        }
    }
    __syncthreads();

    const int nbuf = (t + 1) & 1;
    __nv_bfloat16* __restrict__ Ahd = g_Ah + (size_t)nbuf * Bv * KA;
    __nv_bfloat16* __restrict__ Ald = g_Al + (size_t)nbuf * Bv * KA;
#pragma unroll
    for (int it = 0; it < 4; it++) {
        int item = tid + it * 256;         // 1024 = 64m x 16j
        int ml = item >> 4, j = item & 15;
        float4 gv = *(const float4*)&sG[ml * GS + j * 4];   // i,f,g,o
        int mg = m0 + ml, jg = (n0 >> 2) + j;
        float co = g_c[mg * 512 + jg];
        float iv = sigmoidf_(gv.x);
        float fv = sigmoidf_(gv.y);
        float gg = tanhf(gv.z);
        float ov = sigmoidf_(gv.w);
        float cc = fv * co + iv * gg;
        float hh = ov * tanhf(cc);
        g_c[mg * 512 + jg] = cc;
        g_h[mg * 512 + jg] = hh;
        __nv_bfloat16 hb = __float2bfloat16(hh);
        Ahd[mg * KA + 64 + jg] = hb;
        Ald[mg * KA + 64 + jg] = __float2bfloat16(hh - __bfloat162float(hb));
    }
}

// ---------------- q projection: split-bf16 mma, 64-wide chunks, 4 stages ----------------
#define QA_MAT_A 4608u                 // 32*72*2
#define QA_MAT_B 9216u                 // 64*72*2
#define QA_STAGE (2u * QA_MAT_A + 2u * QA_MAT_B)   // 27648
#define Q_SMEM   (4u * QA_STAGE)       // 110592

__global__ __launch_bounds__(256) void q_mma_kernel(const float* __restrict__ bq, int t) {
    extern __shared__ __align__(16) char smem[];
    const uint32_t sb = smem_u32(smem);
    const int tid = threadIdx.x, wid = tid >> 5, lane = tid & 31;
    const int m0 = (blockIdx.x & 3) * 32;
    const int n0 = (blockIdx.x >> 2) * 64;
    const int nbuf = (t + 1) & 1;
    const __nv_bfloat16* __restrict__ Ah = g_Ah + (size_t)nbuf * Bv * KA + 64;  // h section
    const __nv_bfloat16* __restrict__ Al = g_Al + (size_t)nbuf * Bv * KA + 64;

    const int lrA = tid >> 3, lcA = (tid & 7) * 8;   // A: 32 rows x 8 segs
    const int lrB = tid >> 2, lcB = (tid & 3) * 8;   // B: 64 rows x 2 segs each
#define Q_ISSUE(c, stage) do {                                              \
        uint32_t _s = sb + (uint32_t)(stage) * QA_STAGE;                    \
        uint32_t _oa = (uint32_t)(lrA * 72 + lcA) * 2;                      \
        uint32_t _ob = (uint32_t)(lrB * 72 + lcB) * 2;                      \
        const __nv_bfloat16* _pa = Ah + (size_t)(m0 + lrA) * KA + (c) * 64 + lcA;  \
        const __nv_bfloat16* _pl = Al + (size_t)(m0 + lrA) * KA + (c) * 64 + lcA;  \
        const __nv_bfloat16* _ph = g_WqH + (size_t)(n0 + lrB) * 512 + (c) * 64 + lcB; \
        const __nv_bfloat16* _pw = g_WqL + (size_t)(n0 + lrB) * 512 + (c) * 64 + lcB; \
        cpa16(_s + _oa, _pa);                                               \
        cpa16(_s + QA_MAT_A + _oa, _pl);                                    \
        cpa16(_s + 2 * QA_MAT_A + _ob, _ph);                                \
        cpa16(_s + 2 * QA_MAT_A + _ob + 64, _ph + 32);                      \
        cpa16(_s + 2 * QA_MAT_A + QA_MAT_B + _ob, _pw);                     \
        cpa16(_s + 2 * QA_MAT_A + QA_MAT_B + _ob + 64, _pw + 32);           \
        asm volatile("cp.async.commit_group;" ::: "memory");                \
    } while (0)

    const int wm = wid & 1, wn = wid >> 1;   // warp tile 16m x 16n
    float acc[2][4] = {};

    Q_ISSUE(0, 0);
    Q_ISSUE(1, 1);
    Q_ISSUE(2, 2);
    for (int c = 0; c < 8; c++) {
        if (c < 5) {
            Q_ISSUE(c + 3, (c + 3) & 3);
            asm volatile("cp.async.wait_group 3;" ::: "memory");
        } else if (c == 5) {
            asm volatile("cp.async.wait_group 2;" ::: "memory");
        } else if (c == 6) {
            asm volatile("cp.async.wait_group 1;" ::: "memory");
        } else {
            asm volatile("cp.async.wait_group 0;" ::: "memory");
        }
        __syncthreads();
        const uint32_t sbase = sb + (uint32_t)(c & 3) * QA_STAGE;
#pragma unroll
        for (int ks = 0; ks < 4; ks++) {
            const int kcol = ks * 16 + (lane >> 4) * 8;
            uint32_t af[4], alf[4], bfr[4], blr[4];
            {
                uint32_t r = sbase + (uint32_t)((wm * 16 + (lane & 15)) * 72 + kcol) * 2;
                ldm_x4(af, r);
                ldm_x4(alf, r + QA_MAT_A);
            }
            {
                uint32_t r = sbase + 2 * QA_MAT_A +
                             (uint32_t)((wn * 16 + (lane & 15)) * 72 + kcol) * 2;
                ldm_x4(bfr, r);
                ldm_x4(blr, r + QA_MAT_B);
            }
#pragma unroll
            for (int nt = 0; nt < 2; nt++) {
                mma_bf16(acc[nt], af,  bfr[nt], bfr[2 + nt]);
                mma_bf16(acc[nt], af,  blr[nt], blr[2 + nt]);
                mma_bf16(acc[nt], alf, bfr[nt], bfr[2 + nt]);
            }
        }
        __syncthreads();
    }

    // epilogue: q = acc + bq -> g_q fp32
    const int row = m0 + wm * 16 + (lane >> 2);
#pragma unroll
    for (int nt = 0; nt < 2; nt++) {
        const int col = n0 + wn * 16 + nt * 8 + (lane & 3) * 2;
        float2 b2 = *(const float2*)(bq + col);
        *(float2*)(g_q + (size_t)row * 512 + col) =
            make_float2(acc[nt][0] + b2.x, acc[nt][1] + b2.y);
        *(float2*)(g_q + (size_t)(row + 8) * 512 + col) =
            make_float2(acc[nt][2] + b2.x, acc[nt][3] + b2.y);
    }
}

// ---------------- attention: coalesced + L2-thrash reversal on odd steps ----------------
__global__ __launch_bounds__(256) void attn_kernel(float* __restrict__ dout, int t) {
    const int bx = (t & 1) ? (int)(gridDim.x - 1 - blockIdx.x) : (int)blockIdx.x;
    const int b = bx >> 3, hn = bx & 7;
    const int tid = threadIdx.x;
    const int wid = tid >> 5, lane = tid & 31;
    __shared__ float sq[64];
    __shared__ float ss[512];
    __shared__ float red[8];
    __shared__ float sbc[2];
    __shared__ float sctx[8][64];
    const float scale = 0.125f;   // 1/sqrt(64)

    if (tid < 64) sq[tid] = g_q[(size_t)b * 512 + hn * 64 + tid];
    __syncthreads();

    const __half* __restrict__ Kb = g_K + (size_t)(b * NHv + hn) * Lv * 64;
    const __half* __restrict__ Vb = g_V + (size_t)(b * NHv + hn) * Lv * 64;

    // ---- scores: 8 lanes per row; warp instr = 4 fully-used 128B lines ----
    const int rr = lane >> 3, cc = lane & 7;
    float q8[8];
#pragma unroll
    for (int j = 0; j < 8; j++) q8[j] = sq[cc * 8 + j];
#pragma unroll
    for (int iter = 0; iter < 16; iter++) {
        const int row = iter * 32 + wid * 4 + rr;
        uint4 u = *(const uint4*)(Kb + (size_t)row * 64 + cc * 8);
        const __half2* hp = (const __half2*)&u;
        float s = 0.f;
#pragma unroll
        for (int j = 0; j < 4; j++) {
            float2 kf = __half22float2(hp[j]);
            s += kf.x * q8[j * 2] + kf.y * q8[j * 2 + 1];
        }
        s += __shfl_xor_sync(0xffffffffu, s, 1);
        s += __shfl_xor_sync(0xffffffffu, s, 2);
        s += __shfl_xor_sync(0xffffffffu, s, 4);
        if (cc == 0) ss[row] = s * scale;
    }
    __syncthreads();

    // ---- softmax over ss[512] ----
    float s0 = ss[tid], s1 = ss[tid + 256];
    float mx = fmaxf(s0, s1);
#pragma unroll
    for (int off = 16; off > 0; off >>= 1) mx = fmaxf(mx, __shfl_xor_sync(0xffffffffu, mx, off));
    if (lane == 0) red[wid] = mx;
    __syncthreads();
    if (tid == 0) {
        float m = red[0];
#pragma unroll
        for (int i = 1; i < 8; i++) m = fmaxf(m, red[i]);
        sbc[0] = m;
    }
    __syncthreads();
    mx = sbc[0];
    float e0 = expf(s0 - mx);
    float e1 = expf(s1 - mx);
    float sm = e0 + e1;
#pragma unroll
    for (int off = 16; off > 0; off >>= 1) sm += __shfl_xor_sync(0xffffffffu, sm, off);
    __syncthreads();
    if (lane == 0) red[wid] = sm;
    __syncthreads();
    if (tid == 0) {
        float s = 0.f;
#pragma unroll
        for (int i = 0; i < 8; i++) s += red[i];
        sbc[1] = 1.f / s;
    }
    __syncthreads();
    const float inv = sbc[1];
    float* amap = dout + ATT_OFF + ((size_t)(b * NHv + hn) * HORv + t) * Lv;
    float a0 = e0 * inv, a1 = e1 * inv;
    ss[tid] = a0; ss[tid + 256] = a1;
    amap[tid] = a0; amap[tid + 256] = a1;
    __syncthreads();

    // ---- context: warp owns 64 rows; lane owns d = lane*2,+1 (128B/instr) ----
    float2 acc2 = make_float2(0.f, 0.f);
    const __half* vp = Vb + (size_t)(wid * 64) * 64 + lane * 2;
    const float* sa = ss + wid * 64;
#pragma unroll 8
    for (int l = 0; l < 64; l++) {
        float a = sa[l];
        float2 v = __half22float2(*(const __half2*)(vp + (size_t)l * 64));
        acc2.x += a * v.x;
        acc2.y += a * v.y;
    }
    *(float2*)&sctx[wid][lane * 2] = acc2;
    __syncthreads();
    if (tid < 64) {
        float s = 0.f;
#pragma unroll
        for (int g = 0; g < 8; g++) s += sctx[g][tid];
        g_ctx[(size_t)b * 512 + hn * 64 + tid] = s;
    }
}

// ---------------- pred = ctx @ Wcomb^T + bcomb -> x (bf16 hi/lo) and d_out ----------------
__global__ __launch_bounds__(256) void pred_kernel(float* __restrict__ dout, int t) {
    int w = (blockIdx.x << 3) + (threadIdx.x >> 5);
    int lane = threadIdx.x & 31;
    int m = w >> 6, o = w & 63;
    const float4* a4 = (const float4*)(g_ctx + (size_t)m * Hv);
    const float4* w4 = (const float4*)(g_Wcomb + (size_t)o * Hv);
    float acc = 0.f;
#pragma unroll
    for (int i = 0; i < 4; i++) {
        float4 a = a4[i * 32 + lane], ww = w4[i * 32 + lane];
        acc += a.x * ww.x + a.y * ww.y + a.z * ww.z + a.w * ww.w;
    }
#pragma unroll
    for (int off = 16; off > 0; off >>= 1) acc += __shfl_xor_sync(0xffffffffu, acc, off);
    if (lane == 0) {
        float v = acc + g_bcomb[o];
        const int nbuf = (t + 1) & 1;
        __nv_bfloat16 xb = __float2bfloat16(v);
        g_Ah[(size_t)nbuf * Bv * KA + m * KA + o] = xb;
        g_Al[(size_t)nbuf * Bv * KA + m * KA + o] =
            __float2bfloat16(v - __bfloat162float(xb));
        dout[(size_t)m * HORv * OUTv + t * OUTv + o] = v;
    }
}

// ---------------- host launcher ----------------
extern "C" void kernel_launch(void* const* d_in, const int* in_sizes, int n_in,
                              void* d_out, int out_size) {
    const float* enc  = (const float*)d_in[0];
    const float* h0   = (const float*)d_in[1];
    const float* c0   = (const float*)d_in[2];
    const float* dec  = (const float*)d_in[3];
    const float* W_ih = (const float*)d_in[4];
    const float* W_hh = (const float*)d_in[5];
    const float* b_ih = (const float*)d_in[6];
    const float* b_hh = (const float*)d_in[7];
    const float* Wq   = (const float*)d_in[8];
    const float* bq   = (const float*)d_in[9];
    const float* Wk   = (const float*)d_in[10];
    const float* bk   = (const float*)d_in[11];
    const float* Wv   = (const float*)d_in[12];
    const float* bv   = (const float*)d_in[13];
    const float* Wo   = (const float*)d_in[14];
    const float* bo   = (const float*)d_in[15];
    const float* Wfc  = (const float*)d_in[16];
    const float* bfc  = (const float*)d_in[17];
    float* out = (float*)d_out;

    static cudaStream_t s2 = nullptr;
    static cudaEvent_t evFork = nullptr, evInit = nullptr, evW = nullptr;
    static cudaEvent_t evE1 = nullptr, evJoin = nullptr;
    if (!s2) {
        cudaFuncSetAttribute(kv_mma_kernel, cudaFuncAttributeMaxDynamicSharedMemorySize,
                             KV_SMEM);
        cudaFuncSetAttribute(gates_mma_kernel, cudaFuncAttributeMaxDynamicSharedMemorySize,
                             GATES_SMEM);
        cudaFuncSetAttribute(q_mma_kernel, cudaFuncAttributeMaxDynamicSharedMemorySize,
                             Q_SMEM);
        cudaStreamCreateWithFlags(&s2, cudaStreamNonBlocking);
        cudaEventCreateWithFlags(&evFork, cudaEventDisableTiming);
        cudaEventCreateWithFlags(&evInit, cudaEventDisableTiming);
        cudaEventCreateWithFlags(&evW, cudaEventDisableTiming);
        cudaEventCreateWithFlags(&evE1, cudaEventDisableTiming);
        cudaEventCreateWithFlags(&evJoin, cudaEventDisableTiming);
    }

    const int half4 = (Bv * Lv * Hv) / 8;   // float4 units per half

    // fork side stream: splitW + encF(second half) run under init/encF0/kv0
    cudaEventRecord(evFork, 0);
    cudaStreamWaitEvent(s2, evFork, 0);
    splitW_kernel<<<768, 256, 0, s2>>>(Wk, Wv, Wq);
    cudaEventRecord(evW, s2);
    encF_kernel<<<1024, 256, 0, s2>>>(enc, half4, half4);
    cudaEventRecord(evE1, s2);

    // main stream: init + first-half enc conversion, then first kv half
    init_kernel<<<(BH + 255) / 256, 256>>>(h0, c0, dec);
    cudaEventRecord(evInit, 0);
    encF_kernel<<<1024, 256>>>(enc, 0, half4);
    cudaStreamWaitEvent(0, evW, 0);
    kv_mma_kernel<<<dim3(8, 256), 256, KV_SMEM>>>(bk, bv, 0);
    cudaStreamWaitEvent(0, evE1, 0);
    kv_mma_kernel<<<dim3(8, 256), 256, KV_SMEM>>>(bk, bv, 256);

    // side stream (overlaps with kv halves): weight prep + step-0 gates/q
    cudaStreamWaitEvent(s2, evInit, 0);
    wg_split_kernel<<<(2048 * KA) / 256, 256, 0, s2>>>(W_ih, W_hh, b_ih, b_hh);
    comb_kernel<<<(OUTv * Hv) / 256, 256, 0, s2>>>(Wfc, Wo);
    bcomb_kernel<<<1, 64, 0, s2>>>(Wfc, bo, bfc);
    gates_mma_kernel<<<64, 256, GATES_SMEM, s2>>>(0);
    q_mma_kernel<<<32, 256, Q_SMEM, s2>>>(bq, 0);
    cudaEventRecord(evJoin, s2);
    cudaStreamWaitEvent(0, evJoin, 0);

    // main stream: step 0 tail + remaining steps
    attn_kernel<<<Bv * NHv, 256>>>(out, 0);
    pred_kernel<<<1024, 256>>>(out, 0);
    for (int t = 1; t < HORv; t++) {
        gates_mma_kernel<<<64, 256, GATES_SMEM>>>(t);
        q_mma_kernel<<<32, 256, Q_SMEM>>>(bq, t);
        attn_kernel<<<Bv * NHv, 256>>>(out, t);
        pred_kernel<<<1024, 256>>>(out, t);
    }
}